// round 2
// baseline (speedup 1.0000x reference)
#include <cuda_runtime.h>
#include <math.h>

// Problem constants (fixed by the dataset)
#define NFEAT 128
#define F1    256      // H1*NHID
#define H1    4
#define NHID  64
#define NCLS  16
#define MAXN  50048
#define MAXE  800000

#define NEG_SLOPE 0.2f

// ---------------- scratch (static __device__, no allocation) ----------------
__device__ __align__(16) float g_xw1[MAXN * F1];     // layer1 x@W1
__device__ __align__(16) float g_x2 [MAXN * F1];     // layer1 output (after ELU)
__device__ __align__(16) float g_a1s[MAXN * H1];
__device__ __align__(16) float g_a1d[MAXN * H1];
__device__ __align__(16) float g_xw2[MAXN * NCLS];
__device__ float g_a2s[MAXN];
__device__ float g_a2d[MAXN];
__device__ int   g_cnt[MAXN];
__device__ int   g_off[MAXN];
__device__ int   g_cur[MAXN];
__device__ int   g_bsums[64];
__device__ int   g_srcs[MAXE];         // src node id, bucketed by dst
__device__ int   g_is64;               // 1 if edge_index delivered as int64

__device__ __forceinline__ float leaky(float x) {
    return x > 0.f ? x : NEG_SLOPE * x;
}

// Load edge endpoint: part=0 -> src, part=1 -> dst. Branches on detected dtype.
__device__ __forceinline__ int load_idx(const void* p, int e, int part, int i) {
    if (g_is64) {
        return (int)((const long long*)p)[(long long)part * e + i];
    } else {
        return ((const int*)p)[(long long)part * e + i];
    }
}

// ---------------- dtype probe: sample first 32 int64 slots ----------------
__global__ void detect_kernel(const void* ei, int e, int n) {
    // Safe under both interpretations: reads at most 256 bytes.
    const long long* p = (const long long*)ei;
    int ok64 = 1;
    int cnt = e < 32 ? e : 32;
    for (int i = 0; i < cnt; i++) {
        long long v = p[i];
        if (v < 0 || v >= (long long)n) { ok64 = 0; break; }
    }
    g_is64 = ok64;
}

// ---------------- GEMM1: xw1 = obs[M,128] @ W1[128,256] ----------------
#define BM 64
#define BN 64
#define BK 64
__global__ void gemm1_kernel(const float* __restrict__ A,
                             const float* __restrict__ W, int M) {
    __shared__ float As[BK][68];   // transposed A tile, padded
    __shared__ float Bs[BK][BN];
    const int tx = threadIdx.x & 15;
    const int ty = threadIdx.x >> 4;
    const int row0 = blockIdx.y * BM;
    const int col0 = blockIdx.x * BN;

    float acc[4][4];
#pragma unroll
    for (int i = 0; i < 4; i++)
#pragma unroll
        for (int j = 0; j < 4; j++) acc[i][j] = 0.f;

    for (int kb = 0; kb < NFEAT; kb += BK) {
        // Load A tile (64 rows x 64 k), store transposed As[k][m]
#pragma unroll
        for (int i = 0; i < 4; i++) {
            int idx = threadIdx.x + i * 256;
            int m  = idx >> 4;       // 0..63
            int kq = idx & 15;       // float4 index along K
            int r  = row0 + m;
            float4 v = make_float4(0.f, 0.f, 0.f, 0.f);
            if (r < M) v = *(const float4*)&A[r * NFEAT + kb + kq * 4];
            As[kq * 4 + 0][m] = v.x;
            As[kq * 4 + 1][m] = v.y;
            As[kq * 4 + 2][m] = v.z;
            As[kq * 4 + 3][m] = v.w;
        }
        // Load B tile (64 k x 64 n)
#pragma unroll
        for (int i = 0; i < 4; i++) {
            int idx = threadIdx.x + i * 256;
            int k  = idx >> 4;
            int nq = idx & 15;
            *(float4*)&Bs[k][nq * 4] =
                *(const float4*)&W[(kb + k) * F1 + col0 + nq * 4];
        }
        __syncthreads();
#pragma unroll
        for (int k = 0; k < BK; k++) {
            float4 a = *(float4*)&As[k][ty * 4];
            float4 b = *(float4*)&Bs[k][tx * 4];
            acc[0][0] += a.x * b.x; acc[0][1] += a.x * b.y; acc[0][2] += a.x * b.z; acc[0][3] += a.x * b.w;
            acc[1][0] += a.y * b.x; acc[1][1] += a.y * b.y; acc[1][2] += a.y * b.z; acc[1][3] += a.y * b.w;
            acc[2][0] += a.z * b.x; acc[2][1] += a.z * b.y; acc[2][2] += a.z * b.z; acc[2][3] += a.z * b.w;
            acc[3][0] += a.w * b.x; acc[3][1] += a.w * b.y; acc[3][2] += a.w * b.z; acc[3][3] += a.w * b.w;
        }
        __syncthreads();
    }
#pragma unroll
    for (int i = 0; i < 4; i++) {
        int r = row0 + ty * 4 + i;
        if (r < M) {
            float4 v = make_float4(acc[i][0], acc[i][1], acc[i][2], acc[i][3]);
            *(float4*)&g_xw1[r * F1 + col0 + tx * 4] = v;
        }
    }
}

// ---------------- att1: per-node a_src/a_dst dots (warp per node) ----------------
__global__ void att1_kernel(const float* __restrict__ att_s,
                            const float* __restrict__ att_d, int n) {
    int node = (blockIdx.x * blockDim.x + threadIdx.x) >> 5;
    int lane = threadIdx.x & 31;
    if (node >= n) return;
    int head = lane >> 3;
    const float* x = g_xw1 + node * F1 + lane * 8;
    float4 x0 = *(const float4*)&x[0];
    float4 x1 = *(const float4*)&x[4];
    float4 s0 = *(const float4*)&att_s[lane * 8];
    float4 s1 = *(const float4*)&att_s[lane * 8 + 4];
    float4 d0 = *(const float4*)&att_d[lane * 8];
    float4 d1 = *(const float4*)&att_d[lane * 8 + 4];
    float ps = x0.x*s0.x + x0.y*s0.y + x0.z*s0.z + x0.w*s0.w
             + x1.x*s1.x + x1.y*s1.y + x1.z*s1.z + x1.w*s1.w;
    float pd = x0.x*d0.x + x0.y*d0.y + x0.z*d0.z + x0.w*d0.w
             + x1.x*d1.x + x1.y*d1.y + x1.z*d1.z + x1.w*d1.w;
#pragma unroll
    for (int off = 4; off > 0; off >>= 1) {
        ps += __shfl_down_sync(0xffffffffu, ps, off);
        pd += __shfl_down_sync(0xffffffffu, pd, off);
    }
    if ((lane & 7) == 0) {
        g_a1s[node * H1 + head] = ps;
        g_a1d[node * H1 + head] = pd;
    }
}

// ---------------- CSR build ----------------
__global__ void zero_cnt_kernel(int n) {
    int i = blockIdx.x * blockDim.x + threadIdx.x;
    if (i < n) g_cnt[i] = 0;
}
__global__ void hist_kernel(const void* __restrict__ ei, int e, int n) {
    int i = blockIdx.x * blockDim.x + threadIdx.x;
    if (i < e) {
        int d = load_idx(ei, e, 1, i);
        if (d >= 0 && d < n) atomicAdd(&g_cnt[d], 1);
    }
}
__global__ void scan1_kernel(int n) {
    __shared__ int s[1024];
    int t = threadIdx.x;
    int gid = blockIdx.x * 1024 + t;
    int x = (gid < n) ? g_cnt[gid] : 0;
    s[t] = x;
    __syncthreads();
#pragma unroll
    for (int off = 1; off < 1024; off <<= 1) {
        int v = (t >= off) ? s[t - off] : 0;
        __syncthreads();
        s[t] += v;
        __syncthreads();
    }
    if (gid < n) g_off[gid] = s[t] - x;     // exclusive within block
    if (t == 1023) g_bsums[blockIdx.x] = s[t];
}
__global__ void scan2_kernel(int nb) {
    __shared__ int s[64];
    int t = threadIdx.x;
    int x = (t < nb) ? g_bsums[t] : 0;
    s[t] = x;
    __syncthreads();
#pragma unroll
    for (int off = 1; off < 64; off <<= 1) {
        int v = (t >= off) ? s[t - off] : 0;
        __syncthreads();
        s[t] += v;
        __syncthreads();
    }
    if (t < nb) g_bsums[t] = s[t] - x;      // exclusive block offsets
}
__global__ void scan3_kernel(int n) {
    int gid = blockIdx.x * 1024 + threadIdx.x;
    if (gid < n) {
        int o = g_off[gid] + g_bsums[blockIdx.x];
        g_off[gid] = o;
        g_cur[gid] = o;
    }
}
__global__ void scatter_kernel(const void* __restrict__ ei, int e, int n) {
    int i = blockIdx.x * blockDim.x + threadIdx.x;
    if (i < e) {
        int d = load_idx(ei, e, 1, i);
        int s = load_idx(ei, e, 0, i);
        if (d >= 0 && d < n && s >= 0 && s < n) {
            int p = atomicAdd(&g_cur[d], 1);
            if (p >= 0 && p < MAXE) g_srcs[p] = s;
        }
    }
}

// ---------------- agg1: softmax-weighted aggregation, bias + ELU (warp/node) ----------------
__global__ void agg1_kernel(const float* __restrict__ bias1, int n) {
    int node = (blockIdx.x * blockDim.x + threadIdx.x) >> 5;
    int lane = threadIdx.x & 31;
    if (node >= n) return;

    float4 ad  = *(float4*)&g_a1d[node * H1];
    float4 asn = *(float4*)&g_a1s[node * H1];
    float4 m;
    m.x = leaky(asn.x + ad.x);
    m.y = leaky(asn.y + ad.y);
    m.z = leaky(asn.z + ad.z);
    m.w = leaky(asn.w + ad.w);

    int start = g_off[node];
    int deg   = g_cnt[node];

    // pass 1: per-head max (edges strided across lanes)
    for (int j = lane; j < deg; j += 32) {
        int s = g_srcs[start + j];
        float4 a = *(float4*)&g_a1s[s * H1];
        m.x = fmaxf(m.x, leaky(a.x + ad.x));
        m.y = fmaxf(m.y, leaky(a.y + ad.y));
        m.z = fmaxf(m.z, leaky(a.z + ad.z));
        m.w = fmaxf(m.w, leaky(a.w + ad.w));
    }
#pragma unroll
    for (int off = 16; off > 0; off >>= 1) {
        m.x = fmaxf(m.x, __shfl_xor_sync(0xffffffffu, m.x, off));
        m.y = fmaxf(m.y, __shfl_xor_sync(0xffffffffu, m.y, off));
        m.z = fmaxf(m.z, __shfl_xor_sync(0xffffffffu, m.z, off));
        m.w = fmaxf(m.w, __shfl_xor_sync(0xffffffffu, m.w, off));
    }

    int head = lane >> 3;
    float mh  = (head < 2) ? (head == 0 ? m.x  : m.y)  : (head == 2 ? m.z  : m.w);
    float adh = (head < 2) ? (head == 0 ? ad.x : ad.y) : (head == 2 ? ad.z : ad.w);
    float ash = (head < 2) ? (head == 0 ? asn.x: asn.y): (head == 2 ? asn.z: asn.w);

    // pass 2: weighted sum; lane handles 8 contiguous channels of its head
    float w = __expf(leaky(ash + adh) - mh);   // self loop
    float sumw = w;
    float acc[8];
    {
        const float* xp = g_xw1 + node * F1 + lane * 8;
        float4 u0 = *(const float4*)&xp[0];
        float4 u1 = *(const float4*)&xp[4];
        acc[0] = w * u0.x; acc[1] = w * u0.y; acc[2] = w * u0.z; acc[3] = w * u0.w;
        acc[4] = w * u1.x; acc[5] = w * u1.y; acc[6] = w * u1.z; acc[7] = w * u1.w;
    }
    for (int j = 0; j < deg; j++) {
        int s = g_srcs[start + j];
        float aa = g_a1s[s * H1 + head];
        float wj = __expf(leaky(aa + adh) - mh);
        sumw += wj;
        const float* xp = g_xw1 + s * F1 + lane * 8;
        float4 u0 = *(const float4*)&xp[0];
        float4 u1 = *(const float4*)&xp[4];
        acc[0] += wj * u0.x; acc[1] += wj * u0.y; acc[2] += wj * u0.z; acc[3] += wj * u0.w;
        acc[4] += wj * u1.x; acc[5] += wj * u1.y; acc[6] += wj * u1.z; acc[7] += wj * u1.w;
    }
    float inv = 1.f / sumw;
    int c0 = lane * 8;
    float o[8];
#pragma unroll
    for (int j = 0; j < 8; j++) {
        float v = acc[j] * inv + bias1[c0 + j];
        o[j] = v > 0.f ? v : expm1f(v);   // ELU
    }
    float* xp = g_x2 + node * F1 + c0;
    *(float4*)&xp[0] = make_float4(o[0], o[1], o[2], o[3]);
    *(float4*)&xp[4] = make_float4(o[4], o[5], o[6], o[7]);
}

// ---------------- GEMM2 + att2: xw2 = x2[n,256]@W2[256,16], a2 dots (warp/node) ----------------
__global__ void gemm2_kernel(const float* __restrict__ W2,
                             const float* __restrict__ as2,
                             const float* __restrict__ ad2, int n) {
    __shared__ float Ws[F1 * NCLS + 32];   // padded so lanes 16..31 stay in bounds
    __shared__ float As2[NCLS], Ad2[NCLS];
    for (int i = threadIdx.x; i < F1 * NCLS; i += 256) Ws[i] = W2[i];
    if (threadIdx.x < NCLS) {
        As2[threadIdx.x] = as2[threadIdx.x];
        Ad2[threadIdx.x] = ad2[threadIdx.x];
    }
    for (int i = F1 * NCLS + threadIdx.x; i < F1 * NCLS + 32; i += 256) Ws[i] = 0.f;
    __syncthreads();

    int node = blockIdx.x * 8 + (threadIdx.x >> 5);
    int lane = threadIdx.x & 31;
    if (node >= n) return;

    float acc = 0.f;
    const float* xr = g_x2 + node * F1;
    for (int k0 = 0; k0 < F1; k0 += 32) {
        float v = xr[k0 + lane];
#pragma unroll
        for (int j = 0; j < 32; j++) {
            float xv = __shfl_sync(0xffffffffu, v, j);
            acc += xv * Ws[(k0 + j) * NCLS + lane];   // lanes>=16 read pad, ignored
        }
    }
    if (lane < NCLS) g_xw2[node * NCLS + lane] = acc;
    float ps = (lane < NCLS) ? acc * As2[lane] : 0.f;
    float pd = (lane < NCLS) ? acc * Ad2[lane] : 0.f;
#pragma unroll
    for (int off = 16; off > 0; off >>= 1) {
        ps += __shfl_xor_sync(0xffffffffu, ps, off);
        pd += __shfl_xor_sync(0xffffffffu, pd, off);
    }
    if (lane == 0) {
        g_a2s[node] = ps;
        g_a2d[node] = pd;
    }
}

// ---------------- agg2 + final softmax (warp per node) ----------------
__global__ void agg2_kernel(const float* __restrict__ bias2,
                            float* __restrict__ out, int n) {
    int node = (blockIdx.x * blockDim.x + threadIdx.x) >> 5;
    int lane = threadIdx.x & 31;
    if (node >= n) return;

    float ad = g_a2d[node];
    float e_self = leaky(g_a2s[node] + ad);
    float m = e_self;
    int start = g_off[node];
    int deg   = g_cnt[node];
    for (int j = lane; j < deg; j += 32)
        m = fmaxf(m, leaky(g_a2s[g_srcs[start + j]] + ad));
#pragma unroll
    for (int off = 16; off > 0; off >>= 1)
        m = fmaxf(m, __shfl_xor_sync(0xffffffffu, m, off));

    float w = __expf(e_self - m);
    float sumw = w;
    float acc = (lane < NCLS) ? w * g_xw2[node * NCLS + lane] : 0.f;
    for (int j = 0; j < deg; j++) {
        int s = g_srcs[start + j];
        float wj = __expf(leaky(g_a2s[s] + ad) - m);
        sumw += wj;
        float xv = (lane < NCLS) ? g_xw2[s * NCLS + lane] : 0.f;
        acc += wj * xv;
    }
    float logit = acc / sumw + bias2[lane & 15];

    // softmax over 16 classes (xor reductions stay inside the 16-lane group)
    float mx = logit;
#pragma unroll
    for (int off = 8; off > 0; off >>= 1)
        mx = fmaxf(mx, __shfl_xor_sync(0xffffffffu, mx, off));
    float p = __expf(logit - mx);
    float s16 = p;
#pragma unroll
    for (int off = 8; off > 0; off >>= 1)
        s16 += __shfl_xor_sync(0xffffffffu, s16, off);
    if (lane < NCLS) out[node * NCLS + lane] = p / s16;
}

// ---------------- launch ----------------
extern "C" void kernel_launch(void* const* d_in, const int* in_sizes, int n_in,
                              void* d_out, int out_size) {
    const float* obs  = (const float*)d_in[0];
    const void*  ei   = d_in[1];              // int32 or int64, detected on device
    const float* W1   = (const float*)d_in[2];
    const float* as1  = (const float*)d_in[3];
    const float* ad1  = (const float*)d_in[4];
    const float* b1   = (const float*)d_in[5];
    const float* W2   = (const float*)d_in[6];
    const float* as2  = (const float*)d_in[7];
    const float* ad2  = (const float*)d_in[8];
    const float* b2   = (const float*)d_in[9];
    float* out = (float*)d_out;

    int n = in_sizes[0] / NFEAT;
    int e = in_sizes[1] / 2;

    // dtype probe (1 thread, trivial)
    detect_kernel<<<1, 1>>>(ei, e, n);

    // GEMM1 + attention scalars
    gemm1_kernel<<<dim3(F1 / BN, (n + BM - 1) / BM), 256>>>(obs, W1, n);
    att1_kernel<<<(n + 7) / 8, 256>>>(as1, ad1, n);

    // CSR build (bucket srcs by dst)
    zero_cnt_kernel<<<(n + 255) / 256, 256>>>(n);
    hist_kernel<<<(e + 255) / 256, 256>>>(ei, e, n);
    int nb = (n + 1023) / 1024;
    scan1_kernel<<<nb, 1024>>>(n);
    scan2_kernel<<<1, 64>>>(nb);
    scan3_kernel<<<nb, 1024>>>(n);
    scatter_kernel<<<(e + 255) / 256, 256>>>(ei, e, n);

    // Layer 1 aggregation (+bias, ELU)
    agg1_kernel<<<(n + 7) / 8, 256>>>(b1, n);

    // Layer 2 GEMM + attention scalars
    gemm2_kernel<<<(n + 7) / 8, 256>>>(W2, as2, ad2, n);

    // Layer 2 aggregation + final softmax
    agg2_kernel<<<(n + 7) / 8, 256>>>(b2, out, n);
}

// round 3
// speedup vs baseline: 1.2925x; 1.2925x over previous
#include <cuda_runtime.h>
#include <math.h>

// Problem constants (fixed by the dataset)
#define NFEAT 128
#define F1    256      // H1*NHID
#define H1    4
#define NHID  64
#define NCLS  16
#define MAXN  50048
#define MAXE  800000

#define NEG_SLOPE 0.2f

// ---------------- scratch (static __device__, no allocation) ----------------
__device__ __align__(16) float g_xw1[MAXN * F1];     // layer1 x@W1
__device__ __align__(16) float g_x2 [MAXN * F1];     // layer1 output (after ELU)
__device__ __align__(16) float g_a1s[MAXN * H1];
__device__ __align__(16) float g_a1d[MAXN * H1];
__device__ __align__(16) float g_xw2[MAXN * NCLS];
__device__ float g_a2s[MAXN];
__device__ float g_a2d[MAXN];
__device__ int   g_cnt[MAXN];
__device__ int   g_off[MAXN];
__device__ int   g_cur[MAXN];
__device__ int   g_bsums[64];
__device__ int   g_srcs[MAXE];         // src node id, bucketed by dst
__device__ int   g_is64;               // 1 if edge_index delivered as int64

__device__ __forceinline__ float leaky(float x) {
    return x > 0.f ? x : NEG_SLOPE * x;
}

// Load edge endpoint: part=0 -> src, part=1 -> dst. Branches on detected dtype.
__device__ __forceinline__ int load_idx(const void* p, int e, int part, int i) {
    if (g_is64) {
        return (int)((const long long*)p)[(long long)part * e + i];
    } else {
        return ((const int*)p)[(long long)part * e + i];
    }
}

// ---------------- dtype probe: sample first 32 int64 slots ----------------
__global__ void detect_kernel(const void* ei, int e, int n) {
    const long long* p = (const long long*)ei;
    int ok64 = 1;
    int cnt = e < 32 ? e : 32;
    for (int i = 0; i < cnt; i++) {
        long long v = p[i];
        if (v < 0 || v >= (long long)n) { ok64 = 0; break; }
    }
    g_is64 = ok64;
}

// ---------------- GEMM1: xw1 = obs[M,128] @ W1[128,256] ----------------
// 128x128 block tile, BK=16, 256 threads, 8x8 microtile (split 4+4 with 64 offset)
#define G1_BM 128
#define G1_BN 128
#define G1_BK 16
__global__ void __launch_bounds__(256) gemm1_kernel(
        const float* __restrict__ A, const float* __restrict__ W, int M) {
    __shared__ float As[G1_BK][132];    // transposed, padded
    __shared__ float Bs[G1_BK][G1_BN];
    const int tid = threadIdx.x;
    const int tx = tid & 15;            // 0..15 -> col groups
    const int ty = tid >> 4;            // 0..15 -> row groups
    const int row0 = blockIdx.y * G1_BM;
    const int col0 = blockIdx.x * G1_BN;

    float acc[8][8];
#pragma unroll
    for (int i = 0; i < 8; i++)
#pragma unroll
        for (int j = 0; j < 8; j++) acc[i][j] = 0.f;

    for (int kb = 0; kb < NFEAT; kb += G1_BK) {
        // A tile: 128 rows x 16 k  (512 float4, 2 per thread), store transposed
#pragma unroll
        for (int i = 0; i < 2; i++) {
            int f  = tid + i * 256;
            int r  = f >> 2;            // 0..127
            int kq = f & 3;             // float4 within 16 k
            int gr = row0 + r;
            float4 v = make_float4(0.f, 0.f, 0.f, 0.f);
            if (gr < M) v = *(const float4*)&A[gr * NFEAT + kb + kq * 4];
            As[kq * 4 + 0][r] = v.x;
            As[kq * 4 + 1][r] = v.y;
            As[kq * 4 + 2][r] = v.z;
            As[kq * 4 + 3][r] = v.w;
        }
        // B tile: 16 k x 128 n (512 float4, 2 per thread)
#pragma unroll
        for (int i = 0; i < 2; i++) {
            int f  = tid + i * 256;
            int kr = f >> 5;            // 0..15
            int nq = f & 31;            // float4 within 128 n
            *(float4*)&Bs[kr][nq * 4] =
                *(const float4*)&W[(kb + kr) * F1 + col0 + nq * 4];
        }
        __syncthreads();
#pragma unroll
        for (int k = 0; k < G1_BK; k++) {
            float4 a0 = *(float4*)&As[k][ty * 4];
            float4 a1 = *(float4*)&As[k][ty * 4 + 64];
            float4 b0 = *(float4*)&Bs[k][tx * 4];
            float4 b1 = *(float4*)&Bs[k][tx * 4 + 64];
            float av[8] = {a0.x, a0.y, a0.z, a0.w, a1.x, a1.y, a1.z, a1.w};
            float bv[8] = {b0.x, b0.y, b0.z, b0.w, b1.x, b1.y, b1.z, b1.w};
#pragma unroll
            for (int i = 0; i < 8; i++)
#pragma unroll
                for (int j = 0; j < 8; j++) acc[i][j] += av[i] * bv[j];
        }
        __syncthreads();
    }
    // epilogue
#pragma unroll
    for (int i = 0; i < 8; i++) {
        int r = row0 + ty * 4 + (i & 3) + (i >> 2) * 64;
        if (r < M) {
            *(float4*)&g_xw1[r * F1 + col0 + tx * 4] =
                make_float4(acc[i][0], acc[i][1], acc[i][2], acc[i][3]);
            *(float4*)&g_xw1[r * F1 + col0 + tx * 4 + 64] =
                make_float4(acc[i][4], acc[i][5], acc[i][6], acc[i][7]);
        }
    }
}

// ---------------- att1: per-node a_src/a_dst dots (warp per node) ----------------
__global__ void att1_kernel(const float* __restrict__ att_s,
                            const float* __restrict__ att_d, int n) {
    int node = (blockIdx.x * blockDim.x + threadIdx.x) >> 5;
    int lane = threadIdx.x & 31;
    if (node >= n) return;
    int head = lane >> 3;
    const float* x = g_xw1 + node * F1 + lane * 8;
    float4 x0 = *(const float4*)&x[0];
    float4 x1 = *(const float4*)&x[4];
    float4 s0 = *(const float4*)&att_s[lane * 8];
    float4 s1 = *(const float4*)&att_s[lane * 8 + 4];
    float4 d0 = *(const float4*)&att_d[lane * 8];
    float4 d1 = *(const float4*)&att_d[lane * 8 + 4];
    float ps = x0.x*s0.x + x0.y*s0.y + x0.z*s0.z + x0.w*s0.w
             + x1.x*s1.x + x1.y*s1.y + x1.z*s1.z + x1.w*s1.w;
    float pd = x0.x*d0.x + x0.y*d0.y + x0.z*d0.z + x0.w*d0.w
             + x1.x*d1.x + x1.y*d1.y + x1.z*d1.z + x1.w*d1.w;
#pragma unroll
    for (int off = 4; off > 0; off >>= 1) {
        ps += __shfl_down_sync(0xffffffffu, ps, off);
        pd += __shfl_down_sync(0xffffffffu, pd, off);
    }
    if ((lane & 7) == 0) {
        g_a1s[node * H1 + head] = ps;
        g_a1d[node * H1 + head] = pd;
    }
}

// ---------------- CSR build ----------------
__global__ void zero_cnt_kernel(int n) {
    int i = blockIdx.x * blockDim.x + threadIdx.x;
    if (i < n) g_cnt[i] = 0;
}
__global__ void hist_kernel(const void* __restrict__ ei, int e, int n) {
    int i = blockIdx.x * blockDim.x + threadIdx.x;
    if (i < e) {
        int d = load_idx(ei, e, 1, i);
        if (d >= 0 && d < n) atomicAdd(&g_cnt[d], 1);
    }
}
__global__ void scan1_kernel(int n) {
    __shared__ int s[1024];
    int t = threadIdx.x;
    int gid = blockIdx.x * 1024 + t;
    int x = (gid < n) ? g_cnt[gid] : 0;
    s[t] = x;
    __syncthreads();
#pragma unroll
    for (int off = 1; off < 1024; off <<= 1) {
        int v = (t >= off) ? s[t - off] : 0;
        __syncthreads();
        s[t] += v;
        __syncthreads();
    }
    if (gid < n) g_off[gid] = s[t] - x;
    if (t == 1023) g_bsums[blockIdx.x] = s[t];
}
__global__ void scan2_kernel(int nb) {
    __shared__ int s[64];
    int t = threadIdx.x;
    int x = (t < nb) ? g_bsums[t] : 0;
    s[t] = x;
    __syncthreads();
#pragma unroll
    for (int off = 1; off < 64; off <<= 1) {
        int v = (t >= off) ? s[t - off] : 0;
        __syncthreads();
        s[t] += v;
        __syncthreads();
    }
    if (t < nb) g_bsums[t] = s[t] - x;
}
__global__ void scan3_kernel(int n) {
    int gid = blockIdx.x * 1024 + threadIdx.x;
    if (gid < n) {
        int o = g_off[gid] + g_bsums[blockIdx.x];
        g_off[gid] = o;
        g_cur[gid] = o;
    }
}
__global__ void scatter_kernel(const void* __restrict__ ei, int e, int n) {
    int i = blockIdx.x * blockDim.x + threadIdx.x;
    if (i < e) {
        int d = load_idx(ei, e, 1, i);
        int s = load_idx(ei, e, 0, i);
        if (d >= 0 && d < n && s >= 0 && s < n) {
            int p = atomicAdd(&g_cur[d], 1);
            if (p >= 0 && p < MAXE) g_srcs[p] = s;
        }
    }
}

// ---------------- agg1: softmax aggregation (no max pass), bias + ELU ----------------
__global__ void agg1_kernel(const float* __restrict__ bias1, int n) {
    int node = (blockIdx.x * blockDim.x + threadIdx.x) >> 5;
    int lane = threadIdx.x & 31;
    if (node >= n) return;

    int head = lane >> 3;
    float adh = g_a1d[node * H1 + head];
    float ash = g_a1s[node * H1 + head];

    int start = g_off[node];
    int deg   = g_cnt[node];

    // self loop term
    float w = __expf(leaky(ash + adh));
    float sumw = w;
    float acc[8];
    {
        const float* xp = g_xw1 + node * F1 + lane * 8;
        float4 u0 = *(const float4*)&xp[0];
        float4 u1 = *(const float4*)&xp[4];
        acc[0] = w * u0.x; acc[1] = w * u0.y; acc[2] = w * u0.z; acc[3] = w * u0.w;
        acc[4] = w * u1.x; acc[5] = w * u1.y; acc[6] = w * u1.z; acc[7] = w * u1.w;
    }
    for (int j = 0; j < deg; j++) {
        int s = g_srcs[start + j];
        float aa = g_a1s[s * H1 + head];
        float wj = __expf(leaky(aa + adh));
        sumw += wj;
        const float* xp = g_xw1 + s * F1 + lane * 8;
        float4 u0 = *(const float4*)&xp[0];
        float4 u1 = *(const float4*)&xp[4];
        acc[0] += wj * u0.x; acc[1] += wj * u0.y; acc[2] += wj * u0.z; acc[3] += wj * u0.w;
        acc[4] += wj * u1.x; acc[5] += wj * u1.y; acc[6] += wj * u1.z; acc[7] += wj * u1.w;
    }
    float inv = 1.f / sumw;
    int c0 = lane * 8;
    float o[8];
#pragma unroll
    for (int j = 0; j < 8; j++) {
        float v = acc[j] * inv + bias1[c0 + j];
        o[j] = v > 0.f ? v : expm1f(v);   // ELU
    }
    float* xp = g_x2 + node * F1 + c0;
    *(float4*)&xp[0] = make_float4(o[0], o[1], o[2], o[3]);
    *(float4*)&xp[4] = make_float4(o[4], o[5], o[6], o[7]);
}

// ---------------- GEMM2: xw2 = x2[n,256] @ W2[256,16] ----------------
// 512 rows per block, 256 threads; W2 slice in registers; X tile in smem.
#define G2_ROWS 512
#define G2_BK   16
__global__ void __launch_bounds__(256) gemm2_kernel(
        const float* __restrict__ W2, int n) {
    __shared__ float Xs[G2_ROWS][G2_BK + 1];   // row stride 17 (odd -> conflict-free)
    const int tid = threadIdx.x;
    const int rowblk = blockIdx.x * G2_ROWS;
    const int rbase = tid & 63;
    const int c0 = (tid >> 6) * 4;

    float acc[8][4];
#pragma unroll
    for (int i = 0; i < 8; i++)
#pragma unroll
        for (int j = 0; j < 4; j++) acc[i][j] = 0.f;

    for (int kb = 0; kb < F1; kb += G2_BK) {
        // load X tile: 512 rows x 16 k
#pragma unroll
        for (int i = 0; i < 8; i++) {
            int lr = (tid >> 2) + 64 * i;
            int gr = rowblk + lr;
            float4 v = make_float4(0.f, 0.f, 0.f, 0.f);
            if (gr < n) v = *(const float4*)&g_x2[gr * F1 + kb + (tid & 3) * 4];
            int kc = (tid & 3) * 4;
            Xs[lr][kc + 0] = v.x;
            Xs[lr][kc + 1] = v.y;
            Xs[lr][kc + 2] = v.z;
            Xs[lr][kc + 3] = v.w;
        }
        // W2 slice into registers (broadcast loads, L1-resident)
        float4 wr[G2_BK];
#pragma unroll
        for (int k = 0; k < G2_BK; k++)
            wr[k] = *(const float4*)&W2[(kb + k) * NCLS + c0];
        __syncthreads();
#pragma unroll
        for (int k = 0; k < G2_BK; k++) {
#pragma unroll
            for (int i = 0; i < 8; i++) {
                float xv = Xs[rbase + 64 * i][k];
                acc[i][0] += xv * wr[k].x;
                acc[i][1] += xv * wr[k].y;
                acc[i][2] += xv * wr[k].z;
                acc[i][3] += xv * wr[k].w;
            }
        }
        __syncthreads();
    }
#pragma unroll
    for (int i = 0; i < 8; i++) {
        int gr = rowblk + rbase + 64 * i;
        if (gr < n)
            *(float4*)&g_xw2[gr * NCLS + c0] =
                make_float4(acc[i][0], acc[i][1], acc[i][2], acc[i][3]);
    }
}

// ---------------- att2: a2s/a2d dots (thread per node) ----------------
__global__ void att2_kernel(const float* __restrict__ as2,
                            const float* __restrict__ ad2, int n) {
    int node = blockIdx.x * blockDim.x + threadIdx.x;
    if (node >= n) return;
    float ps = 0.f, pd = 0.f;
#pragma unroll
    for (int q = 0; q < 4; q++) {
        float4 x = *(const float4*)&g_xw2[node * NCLS + q * 4];
        float4 s = *(const float4*)&as2[q * 4];
        float4 d = *(const float4*)&ad2[q * 4];
        ps += x.x*s.x + x.y*s.y + x.z*s.z + x.w*s.w;
        pd += x.x*d.x + x.y*d.y + x.z*d.z + x.w*d.w;
    }
    g_a2s[node] = ps;
    g_a2d[node] = pd;
}

// ---------------- agg2 + final softmax (warp per node, no max pass) ----------------
__global__ void agg2_kernel(const float* __restrict__ bias2,
                            float* __restrict__ out, int n) {
    int node = (blockIdx.x * blockDim.x + threadIdx.x) >> 5;
    int lane = threadIdx.x & 31;
    if (node >= n) return;

    float ad = g_a2d[node];
    float w = __expf(leaky(g_a2s[node] + ad));   // self loop
    float sumw = w;
    float acc = (lane < NCLS) ? w * g_xw2[node * NCLS + lane] : 0.f;
    int start = g_off[node];
    int deg   = g_cnt[node];
    for (int j = 0; j < deg; j++) {
        int s = g_srcs[start + j];
        float wj = __expf(leaky(g_a2s[s] + ad));
        sumw += wj;
        float xv = (lane < NCLS) ? g_xw2[s * NCLS + lane] : 0.f;
        acc += wj * xv;
    }
    float logit = acc / sumw + bias2[lane & 15];

    // softmax over 16 classes
    float mx = logit;
#pragma unroll
    for (int off = 8; off > 0; off >>= 1)
        mx = fmaxf(mx, __shfl_xor_sync(0xffffffffu, mx, off));
    float p = __expf(logit - mx);
    float s16 = p;
#pragma unroll
    for (int off = 8; off > 0; off >>= 1)
        s16 += __shfl_xor_sync(0xffffffffu, s16, off);
    if (lane < NCLS) out[node * NCLS + lane] = p / s16;
}

// ---------------- launch ----------------
extern "C" void kernel_launch(void* const* d_in, const int* in_sizes, int n_in,
                              void* d_out, int out_size) {
    const float* obs  = (const float*)d_in[0];
    const void*  ei   = d_in[1];              // int32 or int64, detected on device
    const float* W1   = (const float*)d_in[2];
    const float* as1  = (const float*)d_in[3];
    const float* ad1  = (const float*)d_in[4];
    const float* b1   = (const float*)d_in[5];
    const float* W2   = (const float*)d_in[6];
    const float* as2  = (const float*)d_in[7];
    const float* ad2  = (const float*)d_in[8];
    const float* b2   = (const float*)d_in[9];
    float* out = (float*)d_out;

    int n = in_sizes[0] / NFEAT;
    int e = in_sizes[1] / 2;

    detect_kernel<<<1, 1>>>(ei, e, n);                         // 1
    zero_cnt_kernel<<<(n + 255) / 256, 256>>>(n);              // 2
    hist_kernel<<<(e + 255) / 256, 256>>>(ei, e, n);           // 3
    gemm1_kernel<<<dim3(F1 / G1_BN, (n + G1_BM - 1) / G1_BM), 256>>>(obs, W1, n); // 4 (ncu slot)
    att1_kernel<<<(n + 7) / 8, 256>>>(as1, ad1, n);            // 5
    int nb = (n + 1023) / 1024;
    scan1_kernel<<<nb, 1024>>>(n);                             // 6
    scan2_kernel<<<1, 64>>>(nb);                               // 7
    scan3_kernel<<<nb, 1024>>>(n);                             // 8
    scatter_kernel<<<(e + 255) / 256, 256>>>(ei, e, n);        // 9
    agg1_kernel<<<(n + 7) / 8, 256>>>(b1, n);                  // 10
    gemm2_kernel<<<(n + G2_ROWS - 1) / G2_ROWS, 256>>>(W2, n); // 11
    att2_kernel<<<(n + 255) / 256, 256>>>(as2, ad2, n);        // 12
    agg2_kernel<<<(n + 7) / 8, 256>>>(b2, out, n);             // 13
}

// round 5
// speedup vs baseline: 1.4394x; 1.1136x over previous
#include <cuda_runtime.h>
#include <cuda_fp16.h>
#include <math.h>

// Problem constants (fixed by the dataset)
#define NFEAT 128
#define F1    256      // H1*NHID
#define H1    4
#define NHID  64
#define NCLS  16
#define MAXN  50048
#define MAXE  800000

#define NEG_SLOPE 0.2f

// ---------------- scratch (static __device__, no allocation) ----------------
__device__ __align__(16) __half g_xw1h[MAXN * F1];   // layer1 x@W1 (fp16 for gathers)
__device__ __align__(16) __half g_x2h [MAXN * F1];   // layer1 output after ELU (fp16)
__device__ __align__(16) float g_a1s[MAXN * H1];
__device__ __align__(16) float g_a1d[MAXN * H1];
__device__ __align__(16) float g_xw2[MAXN * NCLS];
__device__ float g_a2s[MAXN];
__device__ float g_a2d[MAXN];
__device__ int   g_cnt[MAXN];
__device__ int   g_off[MAXN];
__device__ int   g_cur[MAXN];
__device__ int   g_bsums[64];
__device__ int   g_srcs[MAXE];         // src node id, bucketed by dst
__device__ int   g_is64;               // 1 if edge_index delivered as int64

__device__ __forceinline__ float leaky(float x) {
    return x > 0.f ? x : NEG_SLOPE * x;
}

// ---- packed f32x2 helpers (Blackwell FFMA2) ----
__device__ __forceinline__ unsigned long long pack2(float lo, float hi) {
    unsigned long long r;
    asm("mov.b64 %0, {%1, %2};" : "=l"(r) : "f"(lo), "f"(hi));
    return r;
}
__device__ __forceinline__ void unpack2(unsigned long long v, float& lo, float& hi) {
    asm("mov.b64 {%0, %1}, %2;" : "=f"(lo), "=f"(hi) : "l"(v));
}
__device__ __forceinline__ void ffma2(unsigned long long& d,
                                      unsigned long long a, unsigned long long b) {
    asm("fma.rn.f32x2 %0, %1, %2, %0;" : "+l"(d) : "l"(a), "l"(b));
}

// Load edge endpoint: part=0 -> src, part=1 -> dst. Branches on detected dtype.
__device__ __forceinline__ int load_idx(const void* p, int e, int part, int i) {
    if (g_is64) {
        return (int)((const long long*)p)[(long long)part * e + i];
    } else {
        return ((const int*)p)[(long long)part * e + i];
    }
}

// ---------------- dtype probe: sample first 32 int64 slots ----------------
__global__ void detect_kernel(const void* ei, int e, int n) {
    const long long* p = (const long long*)ei;
    int ok64 = 1;
    int cnt = e < 32 ? e : 32;
    for (int i = 0; i < cnt; i++) {
        long long v = p[i];
        if (v < 0 || v >= (long long)n) { ok64 = 0; break; }
    }
    g_is64 = ok64;
}

// ---------------- GEMM1: xw1 = obs[M,128] @ W1[128,256] (FFMA2, fp16 out) ----------------
#define G1_BM 128
#define G1_BN 128
#define G1_BK 16
__global__ void __launch_bounds__(256) gemm1_kernel(
        const float* __restrict__ A, const float* __restrict__ W, int M) {
    __shared__ float As[G1_BK][132];    // transposed, padded
    __shared__ float Bs[G1_BK][G1_BN];
    const int tid = threadIdx.x;
    const int tx = tid & 15;            // col groups
    const int ty = tid >> 4;            // row groups
    const int row0 = blockIdx.y * G1_BM;
    const int col0 = blockIdx.x * G1_BN;

    unsigned long long acc2[8][4];      // 8 rows x 4 col-pairs
#pragma unroll
    for (int i = 0; i < 8; i++)
#pragma unroll
        for (int j = 0; j < 4; j++) acc2[i][j] = 0ull;

    for (int kb = 0; kb < NFEAT; kb += G1_BK) {
#pragma unroll
        for (int i = 0; i < 2; i++) {
            int f  = tid + i * 256;
            int r  = f >> 2;
            int kq = f & 3;
            int gr = row0 + r;
            float4 v = make_float4(0.f, 0.f, 0.f, 0.f);
            if (gr < M) v = *(const float4*)&A[gr * NFEAT + kb + kq * 4];
            As[kq * 4 + 0][r] = v.x;
            As[kq * 4 + 1][r] = v.y;
            As[kq * 4 + 2][r] = v.z;
            As[kq * 4 + 3][r] = v.w;
        }
#pragma unroll
        for (int i = 0; i < 2; i++) {
            int f  = tid + i * 256;
            int kr = f >> 5;
            int nq = f & 31;
            *(float4*)&Bs[kr][nq * 4] =
                *(const float4*)&W[(kb + kr) * F1 + col0 + nq * 4];
        }
        __syncthreads();
#pragma unroll
        for (int k = 0; k < G1_BK; k++) {
            float4 a0 = *(float4*)&As[k][ty * 4];
            float4 a1 = *(float4*)&As[k][ty * 4 + 64];
            float4 b0 = *(float4*)&Bs[k][tx * 4];
            float4 b1 = *(float4*)&Bs[k][tx * 4 + 64];
            unsigned long long bv2[4] = {
                pack2(b0.x, b0.y), pack2(b0.z, b0.w),
                pack2(b1.x, b1.y), pack2(b1.z, b1.w)
            };
            float av[8] = {a0.x, a0.y, a0.z, a0.w, a1.x, a1.y, a1.z, a1.w};
#pragma unroll
            for (int i = 0; i < 8; i++) {
                unsigned long long av2 = pack2(av[i], av[i]);
#pragma unroll
                for (int j = 0; j < 4; j++) ffma2(acc2[i][j], av2, bv2[j]);
            }
        }
        __syncthreads();
    }
    // epilogue: convert to fp16, store as half2 pairs
#pragma unroll
    for (int i = 0; i < 8; i++) {
        int r = row0 + ty * 4 + (i & 3) + (i >> 2) * 64;
        if (r < M) {
            float c0, c1, c2, c3;
            unpack2(acc2[i][0], c0, c1);
            unpack2(acc2[i][1], c2, c3);
            __half2* p0 = (__half2*)&g_xw1h[r * F1 + col0 + tx * 4];
            p0[0] = __floats2half2_rn(c0, c1);
            p0[1] = __floats2half2_rn(c2, c3);
            unpack2(acc2[i][2], c0, c1);
            unpack2(acc2[i][3], c2, c3);
            __half2* p1 = (__half2*)&g_xw1h[r * F1 + col0 + tx * 4 + 64];
            p1[0] = __floats2half2_rn(c0, c1);
            p1[1] = __floats2half2_rn(c2, c3);
        }
    }
}

// ---------------- att1: per-node a_src/a_dst dots (warp per node, fp16 x) ----------------
__global__ void att1_kernel(const float* __restrict__ att_s,
                            const float* __restrict__ att_d, int n) {
    int node = (blockIdx.x * blockDim.x + threadIdx.x) >> 5;
    int lane = threadIdx.x & 31;
    if (node >= n) return;
    int head = lane >> 3;
    uint4 u = *(const uint4*)&g_xw1h[node * F1 + lane * 8];
    float2 f0 = __half22float2(*(__half2*)&u.x);
    float2 f1 = __half22float2(*(__half2*)&u.y);
    float2 f2 = __half22float2(*(__half2*)&u.z);
    float2 f3 = __half22float2(*(__half2*)&u.w);
    float4 s0 = *(const float4*)&att_s[lane * 8];
    float4 s1 = *(const float4*)&att_s[lane * 8 + 4];
    float4 d0 = *(const float4*)&att_d[lane * 8];
    float4 d1 = *(const float4*)&att_d[lane * 8 + 4];
    float ps = f0.x*s0.x + f0.y*s0.y + f1.x*s0.z + f1.y*s0.w
             + f2.x*s1.x + f2.y*s1.y + f3.x*s1.z + f3.y*s1.w;
    float pd = f0.x*d0.x + f0.y*d0.y + f1.x*d0.z + f1.y*d0.w
             + f2.x*d1.x + f2.y*d1.y + f3.x*d1.z + f3.y*d1.w;
#pragma unroll
    for (int off = 4; off > 0; off >>= 1) {
        ps += __shfl_down_sync(0xffffffffu, ps, off);
        pd += __shfl_down_sync(0xffffffffu, pd, off);
    }
    if ((lane & 7) == 0) {
        g_a1s[node * H1 + head] = ps;
        g_a1d[node * H1 + head] = pd;
    }
}

// ---------------- CSR build ----------------
__global__ void zero_cnt_kernel(int n) {
    int i = blockIdx.x * blockDim.x + threadIdx.x;
    if (i < n) g_cnt[i] = 0;
}
__global__ void hist_kernel(const void* __restrict__ ei, int e, int n) {
    int i = blockIdx.x * blockDim.x + threadIdx.x;
    if (i < e) {
        int d = load_idx(ei, e, 1, i);
        if (d >= 0 && d < n) atomicAdd(&g_cnt[d], 1);
    }
}
__global__ void scan1_kernel(int n) {
    __shared__ int s[1024];
    int t = threadIdx.x;
    int gid = blockIdx.x * 1024 + t;
    int x = (gid < n) ? g_cnt[gid] : 0;
    s[t] = x;
    __syncthreads();
#pragma unroll
    for (int off = 1; off < 1024; off <<= 1) {
        int v = (t >= off) ? s[t - off] : 0;
        __syncthreads();
        s[t] += v;
        __syncthreads();
    }
    if (gid < n) g_off[gid] = s[t] - x;
    if (t == 1023) g_bsums[blockIdx.x] = s[t];
}
__global__ void scan2_kernel(int nb) {
    __shared__ int s[64];
    int t = threadIdx.x;
    int x = (t < nb) ? g_bsums[t] : 0;
    s[t] = x;
    __syncthreads();
#pragma unroll
    for (int off = 1; off < 64; off <<= 1) {
        int v = (t >= off) ? s[t - off] : 0;
        __syncthreads();
        s[t] += v;
        __syncthreads();
    }
    if (t < nb) g_bsums[t] = s[t] - x;
}
__global__ void scan3_kernel(int n) {
    int gid = blockIdx.x * 1024 + threadIdx.x;
    if (gid < n) {
        int o = g_off[gid] + g_bsums[blockIdx.x];
        g_off[gid] = o;
        g_cur[gid] = o;
    }
}
__global__ void scatter_kernel(const void* __restrict__ ei, int e, int n) {
    int i = blockIdx.x * blockDim.x + threadIdx.x;
    if (i < e) {
        int d = load_idx(ei, e, 1, i);
        int s = load_idx(ei, e, 0, i);
        if (d >= 0 && d < n && s >= 0 && s < n) {
            int p = atomicAdd(&g_cur[d], 1);
            if (p >= 0 && p < MAXE) g_srcs[p] = s;
        }
    }
}

// ---------------- agg1: softmax aggregation (fp16 gathers), bias + ELU ----------------
__global__ void agg1_kernel(const float* __restrict__ bias1, int n) {
    int node = (blockIdx.x * blockDim.x + threadIdx.x) >> 5;
    int lane = threadIdx.x & 31;
    if (node >= n) return;

    int head = lane >> 3;
    float adh = g_a1d[node * H1 + head];
    float ash = g_a1s[node * H1 + head];

    int start = g_off[node];
    int deg   = g_cnt[node];

    // self loop term
    float w = __expf(leaky(ash + adh));
    float sumw = w;
    float acc[8];
    {
        uint4 u = *(const uint4*)&g_xw1h[node * F1 + lane * 8];
        float2 f0 = __half22float2(*(__half2*)&u.x);
        float2 f1 = __half22float2(*(__half2*)&u.y);
        float2 f2 = __half22float2(*(__half2*)&u.z);
        float2 f3 = __half22float2(*(__half2*)&u.w);
        acc[0] = w * f0.x; acc[1] = w * f0.y; acc[2] = w * f1.x; acc[3] = w * f1.y;
        acc[4] = w * f2.x; acc[5] = w * f2.y; acc[6] = w * f3.x; acc[7] = w * f3.y;
    }
    for (int j = 0; j < deg; j++) {
        int s = g_srcs[start + j];
        float aa = g_a1s[s * H1 + head];
        float wj = __expf(leaky(aa + adh));
        sumw += wj;
        uint4 u = *(const uint4*)&g_xw1h[s * F1 + lane * 8];
        float2 f0 = __half22float2(*(__half2*)&u.x);
        float2 f1 = __half22float2(*(__half2*)&u.y);
        float2 f2 = __half22float2(*(__half2*)&u.z);
        float2 f3 = __half22float2(*(__half2*)&u.w);
        acc[0] += wj * f0.x; acc[1] += wj * f0.y; acc[2] += wj * f1.x; acc[3] += wj * f1.y;
        acc[4] += wj * f2.x; acc[5] += wj * f2.y; acc[6] += wj * f3.x; acc[7] += wj * f3.y;
    }
    float inv = 1.f / sumw;
    int c0 = lane * 8;
    float o[8];
#pragma unroll
    for (int j = 0; j < 8; j++) {
        float v = acc[j] * inv + bias1[c0 + j];
        o[j] = v > 0.f ? v : expm1f(v);   // ELU
    }
    __half2* xp = (__half2*)&g_x2h[node * F1 + c0];
    xp[0] = __floats2half2_rn(o[0], o[1]);
    xp[1] = __floats2half2_rn(o[2], o[3]);
    xp[2] = __floats2half2_rn(o[4], o[5]);
    xp[3] = __floats2half2_rn(o[6], o[7]);
}

// ---------------- GEMM2: xw2 = x2[n,256] @ W2[256,16] (fp16 in) ----------------
#define G2_ROWS 512
#define G2_BK   16
__global__ void __launch_bounds__(256) gemm2_kernel(
        const float* __restrict__ W2, int n) {
    __shared__ float Xs[G2_ROWS][G2_BK + 1];
    const int tid = threadIdx.x;
    const int rowblk = blockIdx.x * G2_ROWS;
    const int rbase = tid & 63;
    const int c0 = (tid >> 6) * 4;

    float acc[8][4];
#pragma unroll
    for (int i = 0; i < 8; i++)
#pragma unroll
        for (int j = 0; j < 4; j++) acc[i][j] = 0.f;

    for (int kb = 0; kb < F1; kb += G2_BK) {
#pragma unroll
        for (int i = 0; i < 8; i++) {
            int lr = (tid >> 2) + 64 * i;
            int gr = rowblk + lr;
            int kc = (tid & 3) * 4;
            float2 fa = make_float2(0.f, 0.f), fb = make_float2(0.f, 0.f);
            if (gr < n) {
                uint2 v = *(const uint2*)&g_x2h[gr * F1 + kb + kc];
                fa = __half22float2(*(__half2*)&v.x);
                fb = __half22float2(*(__half2*)&v.y);
            }
            Xs[lr][kc + 0] = fa.x;
            Xs[lr][kc + 1] = fa.y;
            Xs[lr][kc + 2] = fb.x;
            Xs[lr][kc + 3] = fb.y;
        }
        float4 wr[G2_BK];
#pragma unroll
        for (int k = 0; k < G2_BK; k++)
            wr[k] = *(const float4*)&W2[(kb + k) * NCLS + c0];
        __syncthreads();
#pragma unroll
        for (int k = 0; k < G2_BK; k++) {
#pragma unroll
            for (int i = 0; i < 8; i++) {
                float xv = Xs[rbase + 64 * i][k];
                acc[i][0] += xv * wr[k].x;
                acc[i][1] += xv * wr[k].y;
                acc[i][2] += xv * wr[k].z;
                acc[i][3] += xv * wr[k].w;
            }
        }
        __syncthreads();
    }
#pragma unroll
    for (int i = 0; i < 8; i++) {
        int gr = rowblk + rbase + 64 * i;
        if (gr < n)
            *(float4*)&g_xw2[gr * NCLS + c0] =
                make_float4(acc[i][0], acc[i][1], acc[i][2], acc[i][3]);
    }
}

// ---------------- att2: a2s/a2d dots (thread per node) ----------------
__global__ void att2_kernel(const float* __restrict__ as2,
                            const float* __restrict__ ad2, int n) {
    int node = blockIdx.x * blockDim.x + threadIdx.x;
    if (node >= n) return;
    float ps = 0.f, pd = 0.f;
#pragma unroll
    for (int q = 0; q < 4; q++) {
        float4 x = *(const float4*)&g_xw2[node * NCLS + q * 4];
        float4 s = *(const float4*)&as2[q * 4];
        float4 d = *(const float4*)&ad2[q * 4];
        ps += x.x*s.x + x.y*s.y + x.z*s.z + x.w*s.w;
        pd += x.x*d.x + x.y*d.y + x.z*d.z + x.w*d.w;
    }
    g_a2s[node] = ps;
    g_a2d[node] = pd;
}

// ---------------- agg2 + final softmax (warp per node) ----------------
__global__ void agg2_kernel(const float* __restrict__ bias2,
                            float* __restrict__ out, int n) {
    int node = (blockIdx.x * blockDim.x + threadIdx.x) >> 5;
    int lane = threadIdx.x & 31;
    if (node >= n) return;

    float ad = g_a2d[node];
    float w = __expf(leaky(g_a2s[node] + ad));   // self loop
    float sumw = w;
    float acc = (lane < NCLS) ? w * g_xw2[node * NCLS + lane] : 0.f;
    int start = g_off[node];
    int deg   = g_cnt[node];
    for (int j = 0; j < deg; j++) {
        int s = g_srcs[start + j];
        float wj = __expf(leaky(g_a2s[s] + ad));
        sumw += wj;
        float xv = (lane < NCLS) ? g_xw2[s * NCLS + lane] : 0.f;
        acc += wj * xv;
    }
    float logit = acc / sumw + bias2[lane & 15];

    float mx = logit;
#pragma unroll
    for (int off = 8; off > 0; off >>= 1)
        mx = fmaxf(mx, __shfl_xor_sync(0xffffffffu, mx, off));
    float p = __expf(logit - mx);
    float s16 = p;
#pragma unroll
    for (int off = 8; off > 0; off >>= 1)
        s16 += __shfl_xor_sync(0xffffffffu, s16, off);
    if (lane < NCLS) out[node * NCLS + lane] = p / s16;
}

// ---------------- launch ----------------
extern "C" void kernel_launch(void* const* d_in, const int* in_sizes, int n_in,
                              void* d_out, int out_size) {
    const float* obs  = (const float*)d_in[0];
    const void*  ei   = d_in[1];
    const float* W1   = (const float*)d_in[2];
    const float* as1  = (const float*)d_in[3];
    const float* ad1  = (const float*)d_in[4];
    const float* b1   = (const float*)d_in[5];
    const float* W2   = (const float*)d_in[6];
    const float* as2  = (const float*)d_in[7];
    const float* ad2  = (const float*)d_in[8];
    const float* b2   = (const float*)d_in[9];
    float* out = (float*)d_out;

    int n = in_sizes[0] / NFEAT;
    int e = in_sizes[1] / 2;

    detect_kernel<<<1, 1>>>(ei, e, n);                         // 1
    zero_cnt_kernel<<<(n + 255) / 256, 256>>>(n);              // 2
    hist_kernel<<<(e + 255) / 256, 256>>>(ei, e, n);           // 3
    gemm1_kernel<<<dim3(F1 / G1_BN, (n + G1_BM - 1) / G1_BM), 256>>>(obs, W1, n); // 4 (ncu slot)
    att1_kernel<<<(n + 7) / 8, 256>>>(as1, ad1, n);            // 5
    int nb = (n + 1023) / 1024;
    scan1_kernel<<<nb, 1024>>>(n);                             // 6
    scan2_kernel<<<1, 64>>>(nb);                               // 7
    scan3_kernel<<<nb, 1024>>>(n);                             // 8
    scatter_kernel<<<(e + 255) / 256, 256>>>(ei, e, n);        // 9
    agg1_kernel<<<(n + 7) / 8, 256>>>(b1, n);                  // 10
    gemm2_kernel<<<(n + G2_ROWS - 1) / G2_ROWS, 256>>>(W2, n); // 11
    att2_kernel<<<(n + 255) / 256, 256>>>(as2, ad2, n);        // 12
    agg2_kernel<<<(n + 7) / 8, 256>>>(b2, out, n);             // 13
}

// round 6
// speedup vs baseline: 1.5200x; 1.0560x over previous
#include <cuda_runtime.h>
#include <cuda_fp16.h>
#include <math.h>

// Problem constants (fixed by the dataset)
#define NFEAT 128
#define F1    256      // H1*NHID
#define H1    4
#define NHID  64
#define NCLS  16
#define MAXN  50048
#define MAXE  800000

#define NEG_SLOPE 0.2f

// ---------------- scratch (static __device__, no allocation) ----------------
__device__ __align__(16) __half g_obsh[MAXN * NFEAT];  // obs in fp16 (tail rows stay 0)
__device__ __align__(16) __half g_w1h [NFEAT * F1];    // W1 in fp16
__device__ __align__(16) __half g_xw1h[MAXN * F1];     // layer1 x@W1 (fp16)
__device__ __align__(16) __half g_x2h [MAXN * F1];     // layer1 output after ELU (fp16)
__device__ __align__(16) float g_a1s[MAXN * H1];
__device__ __align__(16) float g_a1d[MAXN * H1];
__device__ __align__(16) float g_xw2[MAXN * NCLS];
__device__ float g_a2s[MAXN];
__device__ float g_a2d[MAXN];
__device__ int   g_cnt[MAXN];
__device__ int   g_off[MAXN];
__device__ int   g_cur[MAXN];
__device__ int   g_bsums[64];
__device__ int   g_srcs[MAXE];         // src node id, bucketed by dst
__device__ int   g_is64;               // 1 if edge_index delivered as int64

__device__ __forceinline__ float leaky(float x) {
    return x > 0.f ? x : NEG_SLOPE * x;
}

// Load edge endpoint: part=0 -> src, part=1 -> dst. Branches on detected dtype.
__device__ __forceinline__ int load_idx(const void* p, int e, int part, int i) {
    if (g_is64) {
        return (int)((const long long*)p)[(long long)part * e + i];
    } else {
        return ((const int*)p)[(long long)part * e + i];
    }
}

// ---------------- dtype probe: sample first 32 int64 slots ----------------
__global__ void detect_kernel(const void* ei, int e, int n) {
    const long long* p = (const long long*)ei;
    int ok64 = 1;
    int cnt = e < 32 ? e : 32;
    for (int i = 0; i < cnt; i++) {
        long long v = p[i];
        if (v < 0 || v >= (long long)n) { ok64 = 0; break; }
    }
    g_is64 = ok64;
}

// ---------------- fp32 -> fp16 conversion ----------------
__global__ void conv_obs_kernel(const float* __restrict__ obs, int m4) {
    int i = blockIdx.x * blockDim.x + threadIdx.x;   // index over float4s
    if (i < m4) {
        float4 v = *(const float4*)&obs[i * 4];
        __half2* dst = (__half2*)&g_obsh[i * 4];
        dst[0] = __floats2half2_rn(v.x, v.y);
        dst[1] = __floats2half2_rn(v.z, v.w);
    }
}
__global__ void conv_w1_kernel(const float* __restrict__ W1) {
    int i = blockIdx.x * blockDim.x + threadIdx.x;   // 8192 float4s
    if (i < NFEAT * F1 / 4) {
        float4 v = *(const float4*)&W1[i * 4];
        __half2* dst = (__half2*)&g_w1h[i * 4];
        dst[0] = __floats2half2_rn(v.x, v.y);
        dst[1] = __floats2half2_rn(v.z, v.w);
    }
}

// ---------------- GEMM1: xw1 = obs[M,128] @ W1[128,256] via HMMA ----------------
// Block: 128 rows x 128 cols, 256 threads = 8 warps (2 M x 4 N), warp tile 64x32.
// A smem row-major [128][72], B smem transposed [n][k] [128][72].
#define G1_PAD 72
__global__ void __launch_bounds__(256, 2) gemm1_mma_kernel(int M) {
    __shared__ __half As [128][G1_PAD];
    __shared__ __half Bst[128][G1_PAD];
    const int tid  = threadIdx.x;
    const int wid  = tid >> 5;
    const int lane = tid & 31;
    const int wm = wid >> 2;          // 0..1
    const int wn = wid & 3;           // 0..3
    const int g  = lane >> 2;         // 0..7
    const int t  = lane & 3;          // 0..3
    const int row0 = blockIdx.y * 128;
    const int col0 = blockIdx.x * 128;

    float c[4][4][4];                 // [mt][nt][4]
#pragma unroll
    for (int mt = 0; mt < 4; mt++)
#pragma unroll
        for (int nt = 0; nt < 4; nt++)
#pragma unroll
            for (int q = 0; q < 4; q++) c[mt][nt][q] = 0.f;

    for (int kb = 0; kb < NFEAT; kb += 64) {
        // A tile: 128 rows x 64 k (2048 uint2, 8 per thread)
#pragma unroll
        for (int i = 0; i < 8; i++) {
            int idx = tid + i * 256;
            int r = idx >> 4;         // 0..127
            int q = idx & 15;         // uint2 within 64 halves
            // rows >= M read zeros (g_obsh is zero-initialized beyond M)
            *(uint2*)&As[r][q * 4] =
                *(const uint2*)&g_obsh[(row0 + r) * NFEAT + kb + q * 4];
        }
        // B tile: 64 k x 128 n, store transposed [n][k]
#pragma unroll
        for (int i = 0; i < 8; i++) {
            int idx = tid + i * 256;
            int kr = idx >> 5;        // 0..63
            int nq = idx & 31;        // 4-col group
            uint2 v = *(const uint2*)&g_w1h[(kb + kr) * F1 + col0 + nq * 4];
            const __half* hv = (const __half*)&v;
            int nb = nq * 4;
            Bst[nb + 0][kr] = hv[0];
            Bst[nb + 1][kr] = hv[1];
            Bst[nb + 2][kr] = hv[2];
            Bst[nb + 3][kr] = hv[3];
        }
        __syncthreads();
#pragma unroll
        for (int ks = 0; ks < 64; ks += 16) {
            // A fragments for 4 m-tiles
            unsigned a[4][4];
#pragma unroll
            for (int mt = 0; mt < 4; mt++) {
                int mr = wm * 64 + mt * 16;
                a[mt][0] = *(const unsigned*)&As[mr + g    ][ks + t * 2    ];
                a[mt][1] = *(const unsigned*)&As[mr + g + 8][ks + t * 2    ];
                a[mt][2] = *(const unsigned*)&As[mr + g    ][ks + t * 2 + 8];
                a[mt][3] = *(const unsigned*)&As[mr + g + 8][ks + t * 2 + 8];
            }
            // B fragments for 4 n-tiles
            unsigned b[4][2];
#pragma unroll
            for (int nt = 0; nt < 4; nt++) {
                int nc = wn * 32 + nt * 8;
                b[nt][0] = *(const unsigned*)&Bst[nc + g][ks + t * 2    ];
                b[nt][1] = *(const unsigned*)&Bst[nc + g][ks + t * 2 + 8];
            }
#pragma unroll
            for (int mt = 0; mt < 4; mt++)
#pragma unroll
                for (int nt = 0; nt < 4; nt++) {
                    asm volatile(
                        "mma.sync.aligned.m16n8k16.row.col.f32.f16.f16.f32 "
                        "{%0,%1,%2,%3}, {%4,%5,%6,%7}, {%8,%9}, {%0,%1,%2,%3};\n"
                        : "+f"(c[mt][nt][0]), "+f"(c[mt][nt][1]),
                          "+f"(c[mt][nt][2]), "+f"(c[mt][nt][3])
                        : "r"(a[mt][0]), "r"(a[mt][1]), "r"(a[mt][2]), "r"(a[mt][3]),
                          "r"(b[nt][0]), "r"(b[nt][1]));
                }
        }
        __syncthreads();
    }
    // epilogue: fp32 acc -> fp16 store
#pragma unroll
    for (int mt = 0; mt < 4; mt++) {
#pragma unroll
        for (int nt = 0; nt < 4; nt++) {
            int row = row0 + wm * 64 + mt * 16 + g;
            int col = col0 + wn * 32 + nt * 8 + t * 2;
            if (row < M)
                *(__half2*)&g_xw1h[row * F1 + col] =
                    __floats2half2_rn(c[mt][nt][0], c[mt][nt][1]);
            if (row + 8 < M)
                *(__half2*)&g_xw1h[(row + 8) * F1 + col] =
                    __floats2half2_rn(c[mt][nt][2], c[mt][nt][3]);
        }
    }
}

// ---------------- att1: per-node a_src/a_dst dots (warp per node, fp16 x) ----------------
__global__ void att1_kernel(const float* __restrict__ att_s,
                            const float* __restrict__ att_d, int n) {
    int node = (blockIdx.x * blockDim.x + threadIdx.x) >> 5;
    int lane = threadIdx.x & 31;
    if (node >= n) return;
    int head = lane >> 3;
    uint4 u = *(const uint4*)&g_xw1h[node * F1 + lane * 8];
    float2 f0 = __half22float2(*(__half2*)&u.x);
    float2 f1 = __half22float2(*(__half2*)&u.y);
    float2 f2 = __half22float2(*(__half2*)&u.z);
    float2 f3 = __half22float2(*(__half2*)&u.w);
    float4 s0 = *(const float4*)&att_s[lane * 8];
    float4 s1 = *(const float4*)&att_s[lane * 8 + 4];
    float4 d0 = *(const float4*)&att_d[lane * 8];
    float4 d1 = *(const float4*)&att_d[lane * 8 + 4];
    float ps = f0.x*s0.x + f0.y*s0.y + f1.x*s0.z + f1.y*s0.w
             + f2.x*s1.x + f2.y*s1.y + f3.x*s1.z + f3.y*s1.w;
    float pd = f0.x*d0.x + f0.y*d0.y + f1.x*d0.z + f1.y*d0.w
             + f2.x*d1.x + f2.y*d1.y + f3.x*d1.z + f3.y*d1.w;
#pragma unroll
    for (int off = 4; off > 0; off >>= 1) {
        ps += __shfl_down_sync(0xffffffffu, ps, off);
        pd += __shfl_down_sync(0xffffffffu, pd, off);
    }
    if ((lane & 7) == 0) {
        g_a1s[node * H1 + head] = ps;
        g_a1d[node * H1 + head] = pd;
    }
}

// ---------------- CSR build ----------------
__global__ void zero_cnt_kernel(int n) {
    int i = blockIdx.x * blockDim.x + threadIdx.x;
    if (i < n) g_cnt[i] = 0;
}
__global__ void hist_kernel(const void* __restrict__ ei, int e, int n) {
    int i = blockIdx.x * blockDim.x + threadIdx.x;
    if (i < e) {
        int d = load_idx(ei, e, 1, i);
        if (d >= 0 && d < n) atomicAdd(&g_cnt[d], 1);
    }
}
__global__ void scan1_kernel(int n) {
    __shared__ int s[1024];
    int t = threadIdx.x;
    int gid = blockIdx.x * 1024 + t;
    int x = (gid < n) ? g_cnt[gid] : 0;
    s[t] = x;
    __syncthreads();
#pragma unroll
    for (int off = 1; off < 1024; off <<= 1) {
        int v = (t >= off) ? s[t - off] : 0;
        __syncthreads();
        s[t] += v;
        __syncthreads();
    }
    if (gid < n) g_off[gid] = s[t] - x;
    if (t == 1023) g_bsums[blockIdx.x] = s[t];
}
__global__ void scan2_kernel(int nb) {
    __shared__ int s[64];
    int t = threadIdx.x;
    int x = (t < nb) ? g_bsums[t] : 0;
    s[t] = x;
    __syncthreads();
#pragma unroll
    for (int off = 1; off < 64; off <<= 1) {
        int v = (t >= off) ? s[t - off] : 0;
        __syncthreads();
        s[t] += v;
        __syncthreads();
    }
    if (t < nb) g_bsums[t] = s[t] - x;
}
__global__ void scan3_kernel(int n) {
    int gid = blockIdx.x * 1024 + threadIdx.x;
    if (gid < n) {
        int o = g_off[gid] + g_bsums[blockIdx.x];
        g_off[gid] = o;
        g_cur[gid] = o;
    }
}
__global__ void scatter_kernel(const void* __restrict__ ei, int e, int n) {
    int i = blockIdx.x * blockDim.x + threadIdx.x;
    if (i < e) {
        int d = load_idx(ei, e, 1, i);
        int s = load_idx(ei, e, 0, i);
        if (d >= 0 && d < n && s >= 0 && s < n) {
            int p = atomicAdd(&g_cur[d], 1);
            if (p >= 0 && p < MAXE) g_srcs[p] = s;
        }
    }
}

// ---------------- agg1: softmax aggregation (fp16 gathers), bias + ELU ----------------
__global__ void agg1_kernel(const float* __restrict__ bias1, int n) {
    int node = (blockIdx.x * blockDim.x + threadIdx.x) >> 5;
    int lane = threadIdx.x & 31;
    if (node >= n) return;

    int head = lane >> 3;
    float adh = g_a1d[node * H1 + head];
    float ash = g_a1s[node * H1 + head];

    int start = g_off[node];
    int deg   = g_cnt[node];

    // self loop term
    float w = __expf(leaky(ash + adh));
    float sumw = w;
    float acc[8];
    {
        uint4 u = *(const uint4*)&g_xw1h[node * F1 + lane * 8];
        float2 f0 = __half22float2(*(__half2*)&u.x);
        float2 f1 = __half22float2(*(__half2*)&u.y);
        float2 f2 = __half22float2(*(__half2*)&u.z);
        float2 f3 = __half22float2(*(__half2*)&u.w);
        acc[0] = w * f0.x; acc[1] = w * f0.y; acc[2] = w * f1.x; acc[3] = w * f1.y;
        acc[4] = w * f2.x; acc[5] = w * f2.y; acc[6] = w * f3.x; acc[7] = w * f3.y;
    }
    for (int j = 0; j < deg; j++) {
        int s = g_srcs[start + j];
        float aa = g_a1s[s * H1 + head];
        float wj = __expf(leaky(aa + adh));
        sumw += wj;
        uint4 u = *(const uint4*)&g_xw1h[s * F1 + lane * 8];
        float2 f0 = __half22float2(*(__half2*)&u.x);
        float2 f1 = __half22float2(*(__half2*)&u.y);
        float2 f2 = __half22float2(*(__half2*)&u.z);
        float2 f3 = __half22float2(*(__half2*)&u.w);
        acc[0] += wj * f0.x; acc[1] += wj * f0.y; acc[2] += wj * f1.x; acc[3] += wj * f1.y;
        acc[4] += wj * f2.x; acc[5] += wj * f2.y; acc[6] += wj * f3.x; acc[7] += wj * f3.y;
    }
    float inv = 1.f / sumw;
    int c0 = lane * 8;
    float o[8];
#pragma unroll
    for (int j = 0; j < 8; j++) {
        float v = acc[j] * inv + bias1[c0 + j];
        o[j] = v > 0.f ? v : expm1f(v);   // ELU
    }
    __half2* xp = (__half2*)&g_x2h[node * F1 + c0];
    xp[0] = __floats2half2_rn(o[0], o[1]);
    xp[1] = __floats2half2_rn(o[2], o[3]);
    xp[2] = __floats2half2_rn(o[4], o[5]);
    xp[3] = __floats2half2_rn(o[6], o[7]);
}

// ---------------- GEMM2: xw2 = x2[n,256] @ W2[256,16] (fp16 in) ----------------
#define G2_ROWS 512
#define G2_BK   16
__global__ void __launch_bounds__(256) gemm2_kernel(
        const float* __restrict__ W2, int n) {
    __shared__ float Xs[G2_ROWS][G2_BK + 1];
    const int tid = threadIdx.x;
    const int rowblk = blockIdx.x * G2_ROWS;
    const int rbase = tid & 63;
    const int c0 = (tid >> 6) * 4;

    float acc[8][4];
#pragma unroll
    for (int i = 0; i < 8; i++)
#pragma unroll
        for (int j = 0; j < 4; j++) acc[i][j] = 0.f;

    for (int kb = 0; kb < F1; kb += G2_BK) {
#pragma unroll
        for (int i = 0; i < 8; i++) {
            int lr = (tid >> 2) + 64 * i;
            int gr = rowblk + lr;
            int kc = (tid & 3) * 4;
            float2 fa = make_float2(0.f, 0.f), fb = make_float2(0.f, 0.f);
            if (gr < n) {
                uint2 v = *(const uint2*)&g_x2h[gr * F1 + kb + kc];
                fa = __half22float2(*(__half2*)&v.x);
                fb = __half22float2(*(__half2*)&v.y);
            }
            Xs[lr][kc + 0] = fa.x;
            Xs[lr][kc + 1] = fa.y;
            Xs[lr][kc + 2] = fb.x;
            Xs[lr][kc + 3] = fb.y;
        }
        float4 wr[G2_BK];
#pragma unroll
        for (int k = 0; k < G2_BK; k++)
            wr[k] = *(const float4*)&W2[(kb + k) * NCLS + c0];
        __syncthreads();
#pragma unroll
        for (int k = 0; k < G2_BK; k++) {
#pragma unroll
            for (int i = 0; i < 8; i++) {
                float xv = Xs[rbase + 64 * i][k];
                acc[i][0] += xv * wr[k].x;
                acc[i][1] += xv * wr[k].y;
                acc[i][2] += xv * wr[k].z;
                acc[i][3] += xv * wr[k].w;
            }
        }
        __syncthreads();
    }
#pragma unroll
    for (int i = 0; i < 8; i++) {
        int gr = rowblk + rbase + 64 * i;
        if (gr < n)
            *(float4*)&g_xw2[gr * NCLS + c0] =
                make_float4(acc[i][0], acc[i][1], acc[i][2], acc[i][3]);
    }
}

// ---------------- att2: a2s/a2d dots (thread per node) ----------------
__global__ void att2_kernel(const float* __restrict__ as2,
                            const float* __restrict__ ad2, int n) {
    int node = blockIdx.x * blockDim.x + threadIdx.x;
    if (node >= n) return;
    float ps = 0.f, pd = 0.f;
#pragma unroll
    for (int q = 0; q < 4; q++) {
        float4 x = *(const float4*)&g_xw2[node * NCLS + q * 4];
        float4 s = *(const float4*)&as2[q * 4];
        float4 d = *(const float4*)&ad2[q * 4];
        ps += x.x*s.x + x.y*s.y + x.z*s.z + x.w*s.w;
        pd += x.x*d.x + x.y*d.y + x.z*d.z + x.w*d.w;
    }
    g_a2s[node] = ps;
    g_a2d[node] = pd;
}

// ---------------- agg2 + final softmax (warp per node) ----------------
__global__ void agg2_kernel(const float* __restrict__ bias2,
                            float* __restrict__ out, int n) {
    int node = (blockIdx.x * blockDim.x + threadIdx.x) >> 5;
    int lane = threadIdx.x & 31;
    if (node >= n) return;

    float ad = g_a2d[node];
    float w = __expf(leaky(g_a2s[node] + ad));   // self loop
    float sumw = w;
    float acc = (lane < NCLS) ? w * g_xw2[node * NCLS + lane] : 0.f;
    int start = g_off[node];
    int deg   = g_cnt[node];
    for (int j = 0; j < deg; j++) {
        int s = g_srcs[start + j];
        float wj = __expf(leaky(g_a2s[s] + ad));
        sumw += wj;
        float xv = (lane < NCLS) ? g_xw2[s * NCLS + lane] : 0.f;
        acc += wj * xv;
    }
    float logit = acc / sumw + bias2[lane & 15];

    float mx = logit;
#pragma unroll
    for (int off = 8; off > 0; off >>= 1)
        mx = fmaxf(mx, __shfl_xor_sync(0xffffffffu, mx, off));
    float p = __expf(logit - mx);
    float s16 = p;
#pragma unroll
    for (int off = 8; off > 0; off >>= 1)
        s16 += __shfl_xor_sync(0xffffffffu, s16, off);
    if (lane < NCLS) out[node * NCLS + lane] = p / s16;
}

// ---------------- launch ----------------
extern "C" void kernel_launch(void* const* d_in, const int* in_sizes, int n_in,
                              void* d_out, int out_size) {
    const float* obs  = (const float*)d_in[0];
    const void*  ei   = d_in[1];
    const float* W1   = (const float*)d_in[2];
    const float* as1  = (const float*)d_in[3];
    const float* ad1  = (const float*)d_in[4];
    const float* b1   = (const float*)d_in[5];
    const float* W2   = (const float*)d_in[6];
    const float* as2  = (const float*)d_in[7];
    const float* ad2  = (const float*)d_in[8];
    const float* b2   = (const float*)d_in[9];
    float* out = (float*)d_out;

    int n = in_sizes[0] / NFEAT;
    int e = in_sizes[1] / 2;

    detect_kernel<<<1, 1>>>(ei, e, n);
    int m4 = n * NFEAT / 4;
    conv_obs_kernel<<<(m4 + 255) / 256, 256>>>(obs, m4);
    conv_w1_kernel<<<(NFEAT * F1 / 4 + 255) / 256, 256>>>(W1);
    zero_cnt_kernel<<<(n + 255) / 256, 256>>>(n);
    hist_kernel<<<(e + 255) / 256, 256>>>(ei, e, n);
    gemm1_mma_kernel<<<dim3(F1 / 128, (n + 127) / 128), 256>>>(n);
    att1_kernel<<<(n + 7) / 8, 256>>>(as1, ad1, n);
    int nb = (n + 1023) / 1024;
    scan1_kernel<<<nb, 1024>>>(n);
    scan2_kernel<<<1, 64>>>(nb);
    scan3_kernel<<<nb, 1024>>>(n);
    scatter_kernel<<<(e + 255) / 256, 256>>>(ei, e, n);
    agg1_kernel<<<(n + 7) / 8, 256>>>(b1, n);
    gemm2_kernel<<<(n + G2_ROWS - 1) / G2_ROWS, 256>>>(W2, n);
    att2_kernel<<<(n + 255) / 256, 256>>>(as2, ad2, n);
    agg2_kernel<<<(n + 7) / 8, 256>>>(b2, out, n);
}

// round 7
// speedup vs baseline: 1.5500x; 1.0198x over previous
#include <cuda_runtime.h>
#include <cuda_fp16.h>
#include <math.h>

// Problem constants (fixed by the dataset)
#define NFEAT 128
#define F1    256      // H1*NHID
#define H1    4
#define NHID  64
#define NCLS  16
#define MAXN  50048
#define MAXE  800000

#define NEG_SLOPE 0.2f

// ---------------- scratch (static __device__, no allocation) ----------------
__device__ __align__(16) __half g_obsh[MAXN * NFEAT];  // obs fp16 (tail rows stay 0)
__device__ __align__(16) __half g_w1h [NFEAT * F1];    // W1 fp16
__device__ __align__(16) __half g_xw1h[MAXN * F1];     // layer1 x@W1 (fp16)
__device__ __align__(16) __half g_x2h [MAXN * F1];     // layer1 output after ELU (fp16)
__device__ __align__(16) float g_a1s[MAXN * H1];
__device__ __align__(16) float g_a1d[MAXN * H1];
__device__ __align__(16) float g_xw2[MAXN * NCLS];
__device__ float g_a2s[MAXN];
__device__ float g_a2d[MAXN];
__device__ int   g_cnt[MAXN];
__device__ int   g_off[MAXN];
__device__ int   g_cur[MAXN];
__device__ int   g_srcs[MAXE];         // src node id, bucketed by dst
__device__ int   g_is64;               // 1 if edge_index delivered as int64
__device__ int   g_scan_blk;           // ordered block id for lookback scan
__device__ unsigned int g_scan_state[64]; // (flag<<30)|sum ; flag 1=A, 2=P

__device__ __forceinline__ float leaky(float x) {
    return x > 0.f ? x : NEG_SLOPE * x;
}

__device__ __forceinline__ int load_idx(const void* p, int e, int part, int i) {
    if (g_is64) {
        return (int)((const long long*)p)[(long long)part * e + i];
    } else {
        return ((const int*)p)[(long long)part * e + i];
    }
}

// ---------------- prep: conversions + zeroing + scan reset + dtype probe ----------------
__global__ void prep_kernel(const float* __restrict__ obs,
                            const float* __restrict__ W1,
                            const void* ei, int e, int n, int m4) {
    int i = blockIdx.x * blockDim.x + threadIdx.x;
    if (i < m4) {                       // obs fp32 -> fp16 (float4 granularity)
        float4 v = *(const float4*)&obs[i * 4];
        __half2* dst = (__half2*)&g_obsh[i * 4];
        dst[0] = __floats2half2_rn(v.x, v.y);
        dst[1] = __floats2half2_rn(v.z, v.w);
    }
    if (i < NFEAT * F1 / 4) {           // W1 fp32 -> fp16
        float4 v = *(const float4*)&W1[i * 4];
        __half2* dst = (__half2*)&g_w1h[i * 4];
        dst[0] = __floats2half2_rn(v.x, v.y);
        dst[1] = __floats2half2_rn(v.z, v.w);
    }
    if (i < n) g_cnt[i] = 0;
    if (i < 64) g_scan_state[i] = 0;
    if (i == 0) {
        g_scan_blk = 0;
        // dtype probe: first 32 slots as int64; all-in-range => int64
        const long long* p = (const long long*)ei;
        int ok64 = 1;
        int cnt = e < 32 ? e : 32;
        for (int k = 0; k < cnt; k++) {
            long long v = p[k];
            if (v < 0 || v >= (long long)n) { ok64 = 0; break; }
        }
        g_is64 = ok64;
    }
}

// ---------------- hist: degree histogram ----------------
__global__ void hist_kernel(const void* __restrict__ ei, int e, int n) {
    int i = blockIdx.x * blockDim.x + threadIdx.x;
    if (i < e) {
        int d = load_idx(ei, e, 1, i);
        if (d >= 0 && d < n) atomicAdd(&g_cnt[d], 1);
    }
}

// ---------------- GEMM1 (HMMA) + fused att1 ----------------
// Block: 128 rows x 128 cols, 256 threads = 8 warps (2 M x 4 N), warp tile 64x32.
#define G1_PAD 72
__global__ void __launch_bounds__(256, 2) gemm1_mma_kernel(
        const float* __restrict__ att_s, const float* __restrict__ att_d, int M) {
    __shared__ __half As [128][G1_PAD];
    __shared__ __half Bst[128][G1_PAD];
    __shared__ float ps_s[128][4];
    __shared__ float pd_s[128][4];
    const int tid  = threadIdx.x;
    const int wid  = tid >> 5;
    const int lane = tid & 31;
    const int wm = wid >> 2;          // 0..1
    const int wn = wid & 3;           // 0..3
    const int g  = lane >> 2;         // 0..7
    const int t  = lane & 3;          // 0..3
    const int row0 = blockIdx.y * 128;
    const int col0 = blockIdx.x * 128;

    float c[4][4][4];
#pragma unroll
    for (int mt = 0; mt < 4; mt++)
#pragma unroll
        for (int nt = 0; nt < 4; nt++)
#pragma unroll
            for (int q = 0; q < 4; q++) c[mt][nt][q] = 0.f;

    for (int kb = 0; kb < NFEAT; kb += 64) {
#pragma unroll
        for (int i = 0; i < 8; i++) {
            int idx = tid + i * 256;
            int r = idx >> 4;
            int q = idx & 15;
            *(uint2*)&As[r][q * 4] =
                *(const uint2*)&g_obsh[(row0 + r) * NFEAT + kb + q * 4];
        }
#pragma unroll
        for (int i = 0; i < 8; i++) {
            int idx = tid + i * 256;
            int kr = idx >> 5;
            int nq = idx & 31;
            uint2 v = *(const uint2*)&g_w1h[(kb + kr) * F1 + col0 + nq * 4];
            const __half* hv = (const __half*)&v;
            int nb = nq * 4;
            Bst[nb + 0][kr] = hv[0];
            Bst[nb + 1][kr] = hv[1];
            Bst[nb + 2][kr] = hv[2];
            Bst[nb + 3][kr] = hv[3];
        }
        __syncthreads();
#pragma unroll
        for (int ks = 0; ks < 64; ks += 16) {
            unsigned a[4][4];
#pragma unroll
            for (int mt = 0; mt < 4; mt++) {
                int mr = wm * 64 + mt * 16;
                a[mt][0] = *(const unsigned*)&As[mr + g    ][ks + t * 2    ];
                a[mt][1] = *(const unsigned*)&As[mr + g + 8][ks + t * 2    ];
                a[mt][2] = *(const unsigned*)&As[mr + g    ][ks + t * 2 + 8];
                a[mt][3] = *(const unsigned*)&As[mr + g + 8][ks + t * 2 + 8];
            }
            unsigned b[4][2];
#pragma unroll
            for (int nt = 0; nt < 4; nt++) {
                int nc = wn * 32 + nt * 8;
                b[nt][0] = *(const unsigned*)&Bst[nc + g][ks + t * 2    ];
                b[nt][1] = *(const unsigned*)&Bst[nc + g][ks + t * 2 + 8];
            }
#pragma unroll
            for (int mt = 0; mt < 4; mt++)
#pragma unroll
                for (int nt = 0; nt < 4; nt++) {
                    asm volatile(
                        "mma.sync.aligned.m16n8k16.row.col.f32.f16.f16.f32 "
                        "{%0,%1,%2,%3}, {%4,%5,%6,%7}, {%8,%9}, {%0,%1,%2,%3};\n"
                        : "+f"(c[mt][nt][0]), "+f"(c[mt][nt][1]),
                          "+f"(c[mt][nt][2]), "+f"(c[mt][nt][3])
                        : "r"(a[mt][0]), "r"(a[mt][1]), "r"(a[mt][2]), "r"(a[mt][3]),
                          "r"(b[nt][0]), "r"(b[nt][1]));
                }
        }
        __syncthreads();
    }

    // epilogue: store fp16 xw1 AND accumulate att dots per row
    float psr[8], pdr[8];   // row index ri = mt*2 + (0: row g, 1: row g+8)
#pragma unroll
    for (int ri = 0; ri < 8; ri++) { psr[ri] = 0.f; pdr[ri] = 0.f; }

#pragma unroll
    for (int mt = 0; mt < 4; mt++) {
#pragma unroll
        for (int nt = 0; nt < 4; nt++) {
            int colg = col0 + wn * 32 + nt * 8 + t * 2;
            float a_s0 = att_s[colg], a_s1 = att_s[colg + 1];
            float a_d0 = att_d[colg], a_d1 = att_d[colg + 1];
            psr[mt*2+0] += c[mt][nt][0] * a_s0 + c[mt][nt][1] * a_s1;
            pdr[mt*2+0] += c[mt][nt][0] * a_d0 + c[mt][nt][1] * a_d1;
            psr[mt*2+1] += c[mt][nt][2] * a_s0 + c[mt][nt][3] * a_s1;
            pdr[mt*2+1] += c[mt][nt][2] * a_d0 + c[mt][nt][3] * a_d1;

            int row = row0 + wm * 64 + mt * 16 + g;
            if (row < M)
                *(__half2*)&g_xw1h[row * F1 + colg] =
                    __floats2half2_rn(c[mt][nt][0], c[mt][nt][1]);
            if (row + 8 < M)
                *(__half2*)&g_xw1h[(row + 8) * F1 + colg] =
                    __floats2half2_rn(c[mt][nt][2], c[mt][nt][3]);
        }
    }
    // reduce over t (4 lanes)
#pragma unroll
    for (int ri = 0; ri < 8; ri++) {
        psr[ri] += __shfl_xor_sync(0xffffffffu, psr[ri], 1);
        psr[ri] += __shfl_xor_sync(0xffffffffu, psr[ri], 2);
        pdr[ri] += __shfl_xor_sync(0xffffffffu, pdr[ri], 1);
        pdr[ri] += __shfl_xor_sync(0xffffffffu, pdr[ri], 2);
    }
    if (t == 0) {
#pragma unroll
        for (int ri = 0; ri < 8; ri++) {
            int row = wm * 64 + (ri >> 1) * 16 + g + (ri & 1) * 8;
            ps_s[row][wn] = psr[ri];
            pd_s[row][wn] = pdr[ri];
        }
    }
    __syncthreads();
    if (tid < 128) {
        int node = row0 + tid;
        if (node < M) {
            int hb = blockIdx.x * 2;   // this col-block owns heads hb, hb+1
            g_a1s[node * H1 + hb    ] = ps_s[tid][0] + ps_s[tid][1];
            g_a1s[node * H1 + hb + 1] = ps_s[tid][2] + ps_s[tid][3];
            g_a1d[node * H1 + hb    ] = pd_s[tid][0] + pd_s[tid][1];
            g_a1d[node * H1 + hb + 1] = pd_s[tid][2] + pd_s[tid][3];
        }
    }
}

// ---------------- single-pass decoupled-lookback scan ----------------
#define FLAG_A 0x40000000u
#define FLAG_P 0x80000000u
#define SUM_MASK 0x3FFFFFFFu
__global__ void scan_kernel(int n) {
    __shared__ int s[1024];
    __shared__ int s_bid;
    __shared__ int s_prefix;
    int t = threadIdx.x;
    if (t == 0) s_bid = atomicAdd(&g_scan_blk, 1);
    __syncthreads();
    int bid = s_bid;
    int gid = bid * 1024 + t;
    int x = (gid < n) ? g_cnt[gid] : 0;
    s[t] = x;
    __syncthreads();
#pragma unroll
    for (int off = 1; off < 1024; off <<= 1) {
        int v = (t >= off) ? s[t - off] : 0;
        __syncthreads();
        s[t] += v;
        __syncthreads();
    }
    int aggregate = s[1023];
    if (t == 0) {
        if (bid == 0) {
            __threadfence();
            atomicExch(&g_scan_state[0], FLAG_P | (unsigned)aggregate);
            s_prefix = 0;
        } else {
            __threadfence();
            atomicExch(&g_scan_state[bid], FLAG_A | (unsigned)aggregate);
            int running = 0;
            for (int p = bid - 1; p >= 0; p--) {
                unsigned st;
                do { st = atomicAdd(&g_scan_state[p], 0u); } while ((st & 0xC0000000u) == 0u);
                running += (int)(st & SUM_MASK);
                if (st & FLAG_P) break;
            }
            __threadfence();
            atomicExch(&g_scan_state[bid], FLAG_P | (unsigned)(running + aggregate));
            s_prefix = running;
        }
    }
    __syncthreads();
    if (gid < n) {
        int o = s_prefix + s[t] - x;   // exclusive
        g_off[gid] = o;
        g_cur[gid] = o;
    }
}

// ---------------- scatter: bucket srcs by dst ----------------
__global__ void scatter_kernel(const void* __restrict__ ei, int e, int n) {
    int i = blockIdx.x * blockDim.x + threadIdx.x;
    if (i < e) {
        int d = load_idx(ei, e, 1, i);
        int s = load_idx(ei, e, 0, i);
        if (d >= 0 && d < n && s >= 0 && s < n) {
            int p = atomicAdd(&g_cur[d], 1);
            if (p >= 0 && p < MAXE) g_srcs[p] = s;
        }
    }
}

// ---------------- agg1: 2 warps per node, softmax aggregation, bias + ELU ----------------
__global__ void agg1_kernel(const float* __restrict__ bias1, int n) {
    int w2 = (blockIdx.x * blockDim.x + threadIdx.x) >> 5;
    int node = w2 >> 1;
    int hs   = w2 & 1;                 // which half of the 256 features
    int lane = threadIdx.x & 31;
    if (node >= n) return;

    int fb = hs * 128 + lane * 4;      // 4 contiguous halves per lane
    int head = fb >> 6;
    float adh = g_a1d[node * H1 + head];
    float ash = g_a1s[node * H1 + head];

    int start = g_off[node];
    int deg   = g_cnt[node];

    float w = __expf(leaky(ash + adh));   // self loop
    float sumw = w;
    float acc0, acc1, acc2, acc3;
    {
        uint2 u = *(const uint2*)&g_xw1h[node * F1 + fb];
        float2 f0 = __half22float2(*(__half2*)&u.x);
        float2 f1 = __half22float2(*(__half2*)&u.y);
        acc0 = w * f0.x; acc1 = w * f0.y; acc2 = w * f1.x; acc3 = w * f1.y;
    }
#pragma unroll 4
    for (int j = 0; j < deg; j++) {
        int s = g_srcs[start + j];
        float aa = g_a1s[s * H1 + head];
        float wj = __expf(leaky(aa + adh));
        sumw += wj;
        uint2 u = *(const uint2*)&g_xw1h[s * F1 + fb];
        float2 f0 = __half22float2(*(__half2*)&u.x);
        float2 f1 = __half22float2(*(__half2*)&u.y);
        acc0 += wj * f0.x; acc1 += wj * f0.y; acc2 += wj * f1.x; acc3 += wj * f1.y;
    }
    float inv = 1.f / sumw;
    float o0 = acc0 * inv + bias1[fb + 0];
    float o1 = acc1 * inv + bias1[fb + 1];
    float o2 = acc2 * inv + bias1[fb + 2];
    float o3 = acc3 * inv + bias1[fb + 3];
    o0 = o0 > 0.f ? o0 : expm1f(o0);
    o1 = o1 > 0.f ? o1 : expm1f(o1);
    o2 = o2 > 0.f ? o2 : expm1f(o2);
    o3 = o3 > 0.f ? o3 : expm1f(o3);
    __half2* xp = (__half2*)&g_x2h[node * F1 + fb];
    xp[0] = __floats2half2_rn(o0, o1);
    xp[1] = __floats2half2_rn(o2, o3);
}

// ---------------- GEMM2: xw2 = x2[n,256] @ W2[256,16] (fp16 in) ----------------
#define G2_ROWS 512
#define G2_BK   16
__global__ void __launch_bounds__(256) gemm2_kernel(
        const float* __restrict__ W2, int n) {
    __shared__ float Xs[G2_ROWS][G2_BK + 1];
    const int tid = threadIdx.x;
    const int rowblk = blockIdx.x * G2_ROWS;
    const int rbase = tid & 63;
    const int c0 = (tid >> 6) * 4;

    float acc[8][4];
#pragma unroll
    for (int i = 0; i < 8; i++)
#pragma unroll
        for (int j = 0; j < 4; j++) acc[i][j] = 0.f;

    for (int kb = 0; kb < F1; kb += G2_BK) {
#pragma unroll
        for (int i = 0; i < 8; i++) {
            int lr = (tid >> 2) + 64 * i;
            int gr = rowblk + lr;
            int kc = (tid & 3) * 4;
            float2 fa = make_float2(0.f, 0.f), fb = make_float2(0.f, 0.f);
            if (gr < n) {
                uint2 v = *(const uint2*)&g_x2h[gr * F1 + kb + kc];
                fa = __half22float2(*(__half2*)&v.x);
                fb = __half22float2(*(__half2*)&v.y);
            }
            Xs[lr][kc + 0] = fa.x;
            Xs[lr][kc + 1] = fa.y;
            Xs[lr][kc + 2] = fb.x;
            Xs[lr][kc + 3] = fb.y;
        }
        float4 wr[G2_BK];
#pragma unroll
        for (int k = 0; k < G2_BK; k++)
            wr[k] = *(const float4*)&W2[(kb + k) * NCLS + c0];
        __syncthreads();
#pragma unroll
        for (int k = 0; k < G2_BK; k++) {
#pragma unroll
            for (int i = 0; i < 8; i++) {
                float xv = Xs[rbase + 64 * i][k];
                acc[i][0] += xv * wr[k].x;
                acc[i][1] += xv * wr[k].y;
                acc[i][2] += xv * wr[k].z;
                acc[i][3] += xv * wr[k].w;
            }
        }
        __syncthreads();
    }
#pragma unroll
    for (int i = 0; i < 8; i++) {
        int gr = rowblk + rbase + 64 * i;
        if (gr < n)
            *(float4*)&g_xw2[gr * NCLS + c0] =
                make_float4(acc[i][0], acc[i][1], acc[i][2], acc[i][3]);
    }
}

// ---------------- att2: a2s/a2d dots (thread per node) ----------------
__global__ void att2_kernel(const float* __restrict__ as2,
                            const float* __restrict__ ad2, int n) {
    int node = blockIdx.x * blockDim.x + threadIdx.x;
    if (node >= n) return;
    float ps = 0.f, pd = 0.f;
#pragma unroll
    for (int q = 0; q < 4; q++) {
        float4 x = *(const float4*)&g_xw2[node * NCLS + q * 4];
        float4 s = *(const float4*)&as2[q * 4];
        float4 d = *(const float4*)&ad2[q * 4];
        ps += x.x*s.x + x.y*s.y + x.z*s.z + x.w*s.w;
        pd += x.x*d.x + x.y*d.y + x.z*d.z + x.w*d.w;
    }
    g_a2s[node] = ps;
    g_a2d[node] = pd;
}

// ---------------- agg2 + final softmax (warp per node, 2 edges/iter) ----------------
__global__ void agg2_kernel(const float* __restrict__ bias2,
                            float* __restrict__ out, int n) {
    int node = (blockIdx.x * blockDim.x + threadIdx.x) >> 5;
    int lane = threadIdx.x & 31;
    if (node >= n) return;

    int half_ = lane >> 4;
    int c     = lane & 15;
    float ad = g_a2d[node];
    float sumw = 0.f, acc = 0.f;
    if (half_ == 0) {                  // self loop counted once
        float w = __expf(leaky(g_a2s[node] + ad));
        sumw = w;
        acc  = w * g_xw2[node * NCLS + c];
    }
    int start = g_off[node];
    int deg   = g_cnt[node];
#pragma unroll 4
    for (int j = half_; j < deg; j += 2) {
        int s = g_srcs[start + j];
        float wj = __expf(leaky(g_a2s[s] + ad));
        sumw += wj;
        acc  += wj * g_xw2[s * NCLS + c];
    }
    sumw += __shfl_xor_sync(0xffffffffu, sumw, 16);
    acc  += __shfl_xor_sync(0xffffffffu, acc, 16);

    float logit = acc / sumw + bias2[c];

    float mx = logit;
#pragma unroll
    for (int off = 8; off > 0; off >>= 1)
        mx = fmaxf(mx, __shfl_xor_sync(0xffffffffu, mx, off));
    float p = __expf(logit - mx);
    float s16 = p;
#pragma unroll
    for (int off = 8; off > 0; off >>= 1)
        s16 += __shfl_xor_sync(0xffffffffu, s16, off);
    if (lane < NCLS) out[node * NCLS + lane] = p / s16;
}

// ---------------- launch ----------------
extern "C" void kernel_launch(void* const* d_in, const int* in_sizes, int n_in,
                              void* d_out, int out_size) {
    const float* obs  = (const float*)d_in[0];
    const void*  ei   = d_in[1];
    const float* W1   = (const float*)d_in[2];
    const float* as1  = (const float*)d_in[3];
    const float* ad1  = (const float*)d_in[4];
    const float* b1   = (const float*)d_in[5];
    const float* W2   = (const float*)d_in[6];
    const float* as2  = (const float*)d_in[7];
    const float* ad2  = (const float*)d_in[8];
    const float* b2   = (const float*)d_in[9];
    float* out = (float*)d_out;

    int n = in_sizes[0] / NFEAT;
    int e = in_sizes[1] / 2;
    int m4 = n * NFEAT / 4;
    int nb = (n + 1023) / 1024;

    prep_kernel<<<(m4 + 255) / 256, 256>>>(obs, W1, ei, e, n, m4);          // 0
    hist_kernel<<<(e + 255) / 256, 256>>>(ei, e, n);                        // 1
    gemm1_mma_kernel<<<dim3(F1 / 128, (n + 127) / 128), 256>>>(as1, ad1, n);// 2
    scan_kernel<<<nb, 1024>>>(n);                                           // 3
    scatter_kernel<<<(e + 255) / 256, 256>>>(ei, e, n);                     // 4
    agg1_kernel<<<(n + 3) / 4, 256>>>(b1, n);                               // 5 (ncu slot)
    gemm2_kernel<<<(n + G2_ROWS - 1) / G2_ROWS, 256>>>(W2, n);              // 6
    att2_kernel<<<(n + 255) / 256, 256>>>(as2, ad2, n);                     // 7
    agg2_kernel<<<(n + 7) / 8, 256>>>(b2, out, n);                          // 8
}